// round 5
// baseline (speedup 1.0000x reference)
#include <cuda_runtime.h>
#include <cuda_fp16.h>
#include <cuda_pipeline.h>

// DiscreteHawkes: T=8192, S=1024, B=8192
// out[i] = relu( mu[s_i] + beta * sum_sp D[t_i, sp] * alpha[sp, s_i] )
// where D[t,sp] = sum_{tp<t} obs[tp,sp] * exp(-beta)^(t-tp)
//
// Kernel 1 (fused prep):
//   - scan blocks: chunked decayed scan along T (fp16 D out), CHUNK=64,
//     WARM=96 halo (a^96 <= e^-9.6 ~ 6.7e-5 for beta >= 0.1).
//   - transpose blocks: alpha -> alphaT packed fp16.
// Kernel 2 (query): warp handles 4 queries, cp.async double-buffered row
//   prefetch into smem; dot fp16 x fp16 -> fp32.

#define T_DIM 8192
#define S_DIM 1024
#define B_DIM 8192
#define CHUNK 64
#define WARM  96
#define NCHUNK (T_DIM / CHUNK)            // 128
#define NSCAN_BLK (NCHUNK * 4)            // 512 (4 col-blocks of 256 per chunk)
#define NTRANS_BLK 512                    // 64sp x 32s tiles over 1024x1024
#define QPW 4                             // queries per warp
#define QPB 16                            // queries per block (4 warps)

// Scratch (allocation-free rule: __device__ globals)
__device__ __half g_Dh[T_DIM * S_DIM];        // 16 MB: D[t, sp] fp16
__device__ __half g_alphaTh[S_DIM * S_DIM];   // 2 MB: alphaT[s, sp] fp16

// ---------------------------------------------------------------------------
// Fused prep: blocks [0, NSCAN_BLK) scan obs; the rest transpose alpha->fp16.
// ---------------------------------------------------------------------------
__global__ __launch_bounds__(256) void prep_kernel(
    const float* __restrict__ alpha,
    const int* __restrict__ obs,
    const float* __restrict__ beta) {
    if (blockIdx.x < NSCAN_BLK) {
        // ---- scan: one column per thread ----
        const int b     = blockIdx.x;
        const int chunk = b >> 2;
        const int c     = (b & 3) * 256 + threadIdx.x;
        const int tbeg  = chunk * CHUNK;
        const int t0    = (tbeg >= WARM) ? (tbeg - WARM) : 0;
        const float a   = expf(-beta[0]);

        const int* __restrict__ col = obs + c;
        __half* __restrict__ dcol = g_Dh + c;

        float d = 0.0f;
#pragma unroll 16
        for (int t = t0; t < tbeg; ++t)
            d = fmaf(a, d, a * (float)col[t * S_DIM]);
#pragma unroll 16
        for (int t = tbeg; t < tbeg + CHUNK; ++t) {
            dcol[t * S_DIM] = __float2half_rn(d);
            d = fmaf(a, d, a * (float)col[t * S_DIM]);
        }
    } else {
        // ---- transpose to fp16: 64(sp) x 32(s) tile ----
        __shared__ float tile[64][33];     // [sp_local][s_local]
        const int bi  = blockIdx.x - NSCAN_BLK;
        const int spb = (bi & 15) * 64;    // 16 sp-tiles
        const int sb  = (bi >> 4) * 32;    // 32 s-tiles
        const int lane = threadIdx.x & 31;
        const int wrp  = threadIdx.x >> 5; // 0..7
#pragma unroll
        for (int j = 0; j < 8; ++j) {
            const int r = wrp + j * 8;     // sp_local 0..63
            tile[r][lane] = alpha[(spb + r) * S_DIM + (sb + lane)];
        }
        __syncthreads();
        __half2* __restrict__ outh2 =
            reinterpret_cast<__half2*>(g_alphaTh);
#pragma unroll
        for (int j = 0; j < 4; ++j) {
            const int sl = wrp + j * 8;    // s_local 0..31
            const __half2 v = __floats2half2_rn(tile[2 * lane][sl],
                                                tile[2 * lane + 1][sl]);
            outh2[(sb + sl) * (S_DIM / 2) + (spb >> 1) + lane] = v;
        }
    }
}

// ---------------------------------------------------------------------------
// Query: warp processes QPW queries with cp.async double-buffered prefetch.
// Stage buffer per warp: D row (1024 half) + alphaT row (1024 half) = 4 KB.
// Each lane copies and later reads the same 4x16B chunks per row.
// ---------------------------------------------------------------------------
__global__ __launch_bounds__(128) void query_kernel(
    const int* __restrict__ tq, const int* __restrict__ sq,
    const float* __restrict__ beta, const float* __restrict__ mu,
    float* __restrict__ out) {
    // [warp][stage][0..1023]=D, [1024..2047]=alphaT
    __shared__ __align__(16) __half sbuf[4][2][2048];

    const int w    = threadIdx.x >> 5;
    const int lane = threadIdx.x & 31;
    const int qbase = blockIdx.x * QPB + w * QPW;

    int ti[QPW], si[QPW];
#pragma unroll
    for (int i = 0; i < QPW; ++i) {
        ti[i] = tq[qbase + i];
        si[i] = sq[qbase + i];
    }

    const char* __restrict__ dbase = (const char*)g_Dh;
    const char* __restrict__ abase = (const char*)g_alphaTh;

    // stage-fill: 8 x 16B cp.async per lane (4 for D, 4 for alphaT)
    auto prefetch = [&](int st, int i) {
        const char* dsrc = dbase + (size_t)ti[i] * (S_DIM * 2);
        const char* asrc = abase + (size_t)si[i] * (S_DIM * 2);
        char* ddst = (char*)&sbuf[w][st][0];
        char* adst = (char*)&sbuf[w][st][1024];
#pragma unroll
        for (int k = 0; k < 4; ++k) {
            const int off = (k * 32 + lane) * 16;
            __pipeline_memcpy_async(ddst + off, dsrc + off, 16);
            __pipeline_memcpy_async(adst + off, asrc + off, 16);
        }
        __pipeline_commit();
    };

    prefetch(0, 0);
    const float bt = beta[0];

#pragma unroll
    for (int i = 0; i < QPW; ++i) {
        if (i < QPW - 1) prefetch((i + 1) & 1, i + 1);
        __pipeline_wait_prior(i < QPW - 1 ? 1 : 0);

        const uint4* du = (const uint4*)&sbuf[w][i & 1][0];
        const uint4* au = (const uint4*)&sbuf[w][i & 1][1024];

        float acc = 0.0f;
#pragma unroll
        for (int k = 0; k < 4; ++k) {
            const int c = k * 32 + lane;
            const uint4 dv = du[c];
            const uint4 av = au[c];
            const __half2* dh = reinterpret_cast<const __half2*>(&dv);
            const __half2* ah = reinterpret_cast<const __half2*>(&av);
#pragma unroll
            for (int j = 0; j < 4; ++j) {
                const float2 df = __half22float2(dh[j]);
                const float2 af = __half22float2(ah[j]);
                acc = fmaf(df.x, af.x, acc);
                acc = fmaf(df.y, af.y, acc);
            }
        }
#pragma unroll
        for (int o = 16; o; o >>= 1)
            acc += __shfl_down_sync(0xffffffffu, acc, o);

        if (lane == 0)
            out[qbase + i] = fmaxf(fmaf(bt, acc, mu[si[i]]), 0.0f);
    }
}

// ---------------------------------------------------------------------------
extern "C" void kernel_launch(void* const* d_in, const int* in_sizes, int n_in,
                              void* d_out, int out_size) {
    const int*   t     = (const int*)d_in[0];
    const int*   s     = (const int*)d_in[1];
    const int*   obs   = (const int*)d_in[2];
    const float* alpha = (const float*)d_in[3];
    const float* beta  = (const float*)d_in[4];
    const float* mu    = (const float*)d_in[5];
    float* out = (float*)d_out;
    (void)in_sizes; (void)n_in; (void)out_size;

    prep_kernel<<<NSCAN_BLK + NTRANS_BLK, 256>>>(alpha, obs, beta);
    query_kernel<<<B_DIM / QPB, 128>>>(t, s, beta, mu, out);
}

// round 7
// speedup vs baseline: 1.3893x; 1.3893x over previous
#include <cuda_runtime.h>
#include <cuda_fp16.h>

// DiscreteHawkes: T=8192, S=1024, B=8192
// out[i] = relu( mu[s_i] + beta * sum_sp D[t_i, sp] * alpha[sp, s_i] )
// where D[t,sp] = sum_{tp<t} obs[tp,sp] * exp(-beta)^(t-tp)
//
// Kernel 1 (fused prep):
//   - scan blocks: chunked decayed scan along T (fp16 D out), CHUNK=128,
//     WARM=128 halo (a^128 <= e^-12.8 ~ 2.8e-6 for beta >= 0.1), unroll 32.
//   - transpose blocks: alpha -> alphaT packed fp16.
// Kernel 2 (query): 1 query per warp, 2048 blocks x 128 threads;
//   fp16 D row x fp16 alphaT row, fp32 accumulate.

#define T_DIM 8192
#define S_DIM 1024
#define B_DIM 8192
#define CHUNK 128
#define WARM  128
#define NCHUNK (T_DIM / CHUNK)            // 64
#define NSCAN_BLK (NCHUNK * 4)            // 256 (4 col-blocks of 256 per chunk)
#define NTRANS_BLK 512                    // 64sp x 32s tiles over 1024x1024

// Scratch (allocation-free rule: __device__ globals)
__device__ __half g_Dh[T_DIM * S_DIM];        // 16 MB: D[t, sp] fp16
__device__ __half g_alphaTh[S_DIM * S_DIM];   // 2 MB: alphaT[s, sp] fp16

// ---------------------------------------------------------------------------
// Fused prep: blocks [0, NSCAN_BLK) scan obs; the rest transpose alpha->fp16.
// ---------------------------------------------------------------------------
__global__ __launch_bounds__(256) void prep_kernel(
    const float* __restrict__ alpha,
    const int* __restrict__ obs,
    const float* __restrict__ beta) {
    if (blockIdx.x < NSCAN_BLK) {
        // ---- scan: one column per thread, deep unroll for MLP ----
        const int b     = blockIdx.x;
        const int chunk = b >> 2;
        const int c     = (b & 3) * 256 + threadIdx.x;
        const int tbeg  = chunk * CHUNK;
        const int t0    = (tbeg >= WARM) ? (tbeg - WARM) : 0;
        const float a   = expf(-beta[0]);

        const int* __restrict__ col = obs + c;
        __half* __restrict__ dcol = g_Dh + c;

        float d = 0.0f;
#pragma unroll 32
        for (int t = t0; t < tbeg; ++t)
            d = fmaf(a, d, a * (float)col[t * S_DIM]);
#pragma unroll 32
        for (int t = tbeg; t < tbeg + CHUNK; ++t) {
            dcol[t * S_DIM] = __float2half_rn(d);
            d = fmaf(a, d, a * (float)col[t * S_DIM]);
        }
    } else {
        // ---- transpose to fp16: 64(sp) x 32(s) tile ----
        __shared__ float tile[64][33];     // [sp_local][s_local]
        const int bi  = blockIdx.x - NSCAN_BLK;
        const int spb = (bi & 15) * 64;    // 16 sp-tiles
        const int sb  = (bi >> 4) * 32;    // 32 s-tiles
        const int lane = threadIdx.x & 31;
        const int wrp  = threadIdx.x >> 5; // 0..7
#pragma unroll
        for (int j = 0; j < 8; ++j) {
            const int r = wrp + j * 8;     // sp_local 0..63
            tile[r][lane] = alpha[(spb + r) * S_DIM + (sb + lane)];
        }
        __syncthreads();
        __half2* __restrict__ outh2 =
            reinterpret_cast<__half2*>(g_alphaTh);
#pragma unroll
        for (int j = 0; j < 4; ++j) {
            const int sl = wrp + j * 8;    // s_local 0..31
            const __half2 v = __floats2half2_rn(tile[2 * lane][sl],
                                                tile[2 * lane + 1][sl]);
            outh2[(sb + sl) * (S_DIM / 2) + (spb >> 1) + lane] = v;
        }
    }
}

// ---------------------------------------------------------------------------
// Query: 1 query per warp, 4 warps/block, 2048 blocks.
// Per lane: 4x uint4 (D) + 4x uint4 (alphaT), all issued before use.
// ---------------------------------------------------------------------------
__global__ __launch_bounds__(128) void query_kernel(
    const int* __restrict__ tq, const int* __restrict__ sq,
    const float* __restrict__ beta, const float* __restrict__ mu,
    float* __restrict__ out) {
    const int q    = blockIdx.x * 4 + (threadIdx.x >> 5);
    const int lane = threadIdx.x & 31;
    const int ti = tq[q];
    const int si = sq[q];

    const uint4* __restrict__ drow =
        reinterpret_cast<const uint4*>(g_Dh + (size_t)ti * S_DIM);
    const uint4* __restrict__ arow =
        reinterpret_cast<const uint4*>(g_alphaTh + (size_t)si * S_DIM);

    // issue all 8 loads first (max MLP)
    uint4 dv[4], av[4];
#pragma unroll
    for (int k = 0; k < 4; ++k) {
        dv[k] = drow[k * 32 + lane];
        av[k] = arow[k * 32 + lane];
    }

    float acc = 0.0f;
#pragma unroll
    for (int k = 0; k < 4; ++k) {
        const __half2* dh = reinterpret_cast<const __half2*>(&dv[k]);
        const __half2* ah = reinterpret_cast<const __half2*>(&av[k]);
#pragma unroll
        for (int j = 0; j < 4; ++j) {
            const float2 df = __half22float2(dh[j]);
            const float2 af = __half22float2(ah[j]);
            acc = fmaf(df.x, af.x, acc);
            acc = fmaf(df.y, af.y, acc);
        }
    }
#pragma unroll
    for (int o = 16; o; o >>= 1)
        acc += __shfl_down_sync(0xffffffffu, acc, o);

    if (lane == 0)
        out[q] = fmaxf(fmaf(beta[0], acc, mu[si]), 0.0f);
}

// ---------------------------------------------------------------------------
extern "C" void kernel_launch(void* const* d_in, const int* in_sizes, int n_in,
                              void* d_out, int out_size) {
    const int*   t     = (const int*)d_in[0];
    const int*   s     = (const int*)d_in[1];
    const int*   obs   = (const int*)d_in[2];
    const float* alpha = (const float*)d_in[3];
    const float* beta  = (const float*)d_in[4];
    const float* mu    = (const float*)d_in[5];
    float* out = (float*)d_out;
    (void)in_sizes; (void)n_in; (void)out_size;

    prep_kernel<<<NSCAN_BLK + NTRANS_BLK, 256>>>(alpha, obs, beta);
    query_kernel<<<B_DIM / 4, 128>>>(t, s, beta, mu, out);
}